// round 17
// baseline (speedup 1.0000x reference)
#include <cuda_runtime.h>

#define NR    8192
#define NQ    4096
#define KNN_K 16
#define C4    64            // 256 channels / 4 (float4)

#define WPB          28
#define THREADS      (WPB * 32)              // 896
#define KNN_BLOCKS   ((NQ + WPB - 1) / WPB)  // 147
#define SAMPLE_ITERS 32                      // 1024 samples (refs 0..1023, raw order)
#define BUF_CAP      384                     // P(overflow) ~ 2e-8/query (Gamma16 tail)
#define SLACK        1e-3f                   // >> all rounding gaps in play (~1e-5)

#define CD     32                            // cells per dim (x, y)
#define C2     (CD * CD)                     // 1024
#define GLO    (-4.0f)
#define INV_CW (4.0f)                        // cell width 0.25 over [-4, 4]

typedef unsigned long long ull;

__device__ int g_knn_idx[NQ * KNN_K];

// q2/r2: jnp.sum(x*x) = sequential add of rn squares (no FMA).
__device__ __forceinline__ float sq3(float x, float y, float z) {
    return __fadd_rn(__fadd_rn(__fmul_rn(x, x), __fmul_rn(y, y)), __fmul_rn(z, z));
}
// cross: XLA dot accumulation = fmuladd chain (seed = rn product).
__device__ __forceinline__ float dot3_fma(float ax, float ay, float az,
                                          float bx, float by, float bz) {
    return __fmaf_rn(az, bz, __fmaf_rn(ay, by, __fmul_rn(ax, bx)));
}
// Lexicographic (dist, idx) as one sortable u64 (survivor buffer only).
__device__ __forceinline__ ull make_key(float d, int r) {
    unsigned b = __float_as_uint(d);
    b ^= ((unsigned)((int)b >> 31)) | 0x80000000u;
    return ((ull)b << 32) | (unsigned)r;
}
// Monotone, clamped cell index (same function for binning and range bounds).
__device__ __forceinline__ int cell_of(float v) {
    int c = (int)floorf((v - GLO) * INV_CW);
    return min(CD - 1, max(0, c));
}

// Float-only bitonic sort of 32 lane values; returns 16th smallest (all lanes).
__device__ __forceinline__ float warp_16th(float sd, int lane) {
#pragma unroll
    for (int kk = 2; kk <= 32; kk <<= 1) {
#pragma unroll
        for (int j = kk >> 1; j > 0; j >>= 1) {
            const float o = __shfl_xor_sync(0xffffffffu, sd, j);
            const bool keepMin = (((lane & j) == 0) == ((lane & kk) == 0));
            sd = keepMin ? fminf(sd, o) : fmaxf(sd, o);
        }
    }
    return __shfl_sync(0xffffffffu, sd, KNN_K - 1);
}

// One warp per query. In-block (x,y) counting sort of refs -> phase 2 scans
// only cell rows intersecting the tau-ball rectangle. Histogram fused into
// the staging fill; 1024-point sample for tau, 384-deep survivor buffers.
__global__ void __launch_bounds__(THREADS, 1) knn_kernel(
        const float* __restrict__ xyz_prev,
        const float* __restrict__ xyz_cur) {
    extern __shared__ unsigned char smraw[];
    float4* sref   = (float4*)smraw;                                   // 128 KB
    ull*    bufs   = (ull*)(smraw + NR * sizeof(float4));              // 84 KB
    int*    cstart = (int*)(smraw + NR * sizeof(float4) + WPB * BUF_CAP * sizeof(ull));
    int*    ccur   = cstart + C2 + 1;                                  // [C2]

    const int tid  = threadIdx.x;
    const int warp = tid >> 5;
    const int lane = tid & 31;

    // 1. zero counters, then stage refs in RAW order with r2 + fused histogram
    for (int i = tid; i < C2; i += THREADS) ccur[i] = 0;
    __syncthreads();
    for (int i = tid; i < NR; i += THREADS) {
        const float x = xyz_prev[3 * i + 0];
        const float y = xyz_prev[3 * i + 1];
        const float z = xyz_prev[3 * i + 2];
        sref[i] = make_float4(x, y, z, sq3(x, y, z));
        atomicAdd(&ccur[cell_of(y) * CD + cell_of(x)], 1);
    }
    __syncthreads();

    // 2a. warp 0: exclusive prefix over 1024 cells (lane owns 32 cells)
    if (warp == 0) {
        const int c0 = lane * 32;
        int s = 0;
#pragma unroll
        for (int k = 0; k < 32; ++k) s += ccur[c0 + k];
        int excl = s;
#pragma unroll
        for (int off = 1; off < 32; off <<= 1) {
            const int v = __shfl_up_sync(0xffffffffu, excl, off);
            if (lane >= off) excl += v;
        }
        excl -= s;
        int run = excl;
#pragma unroll
        for (int k = 0; k < 32; ++k) {
            const int c = ccur[c0 + k];
            cstart[c0 + k] = run;
            ccur[c0 + k] = run;          // scatter cursor
            run += c;
        }
        if (lane == 31) cstart[C2] = NR;
    }

    // 2b. all warps: phase-1 tau from raw sref[0..1024) (concurrent w/ prefix)
    const int q = blockIdx.x * WPB + warp;
    const bool active = (q < NQ);
    float qx = 0, qy = 0, qz = 0, q2 = 0, R2 = 0, Rr = 0;
    if (active) {
        qx = xyz_cur[3 * q + 0];
        qy = xyz_cur[3 * q + 1];
        qz = xyz_cur[3 * q + 2];
        q2 = sq3(qx, qy, qz);

        const float INF = __int_as_float(0x7f800000);
        float m0 = INF, m1 = INF, m2 = INF, m3 = INF;
#pragma unroll
        for (int i = 0; i < SAMPLE_ITERS; i += 4) {
            const float4 p0 = sref[lane + 32 * (i + 0)];
            const float4 p1 = sref[lane + 32 * (i + 1)];
            const float4 p2 = sref[lane + 32 * (i + 2)];
            const float4 p3 = sref[lane + 32 * (i + 3)];
            m0 = fminf(m0, __fmaf_rn(-2.0f, dot3_fma(qx, qy, qz, p0.x, p0.y, p0.z), p0.w));
            m1 = fminf(m1, __fmaf_rn(-2.0f, dot3_fma(qx, qy, qz, p1.x, p1.y, p1.z), p1.w));
            m2 = fminf(m2, __fmaf_rn(-2.0f, dot3_fma(qx, qy, qz, p2.x, p2.y, p2.z), p2.w));
            m3 = fminf(m3, __fmaf_rn(-2.0f, dot3_fma(qx, qy, qz, p3.x, p3.y, p3.z), p3.w));
        }
        const float tau_t = warp_16th(fminf(fminf(m0, m1), fminf(m2, m3)), lane);
        // d-space superset threshold (>= true d16) + slack for rounding gaps
        R2 = fmaxf(tau_t + q2 + SLACK, 0.0f) + SLACK;
        Rr = sqrtf(R2) + 1e-3f;
    }
    __syncthreads();

    // 3. scatter refs cell-sorted (re-read gmem; raw sref is dead now)
    for (int r = tid; r < NR; r += THREADS) {
        const float x = xyz_prev[3 * r + 0];
        const float y = xyz_prev[3 * r + 1];
        const float z = xyz_prev[3 * r + 2];
        const int pos = atomicAdd(&ccur[cell_of(y) * CD + cell_of(x)], 1);
        sref[pos] = make_float4(x, y, z, __int_as_float(r));
    }
    __syncthreads();
    if (!active) return;                 // after last block-wide sync

    ull* wbuf = bufs + warp * BUF_CAP;

    // 4. phase-2: scan cell rows of the rectangle, ballot-compact survivors
    const int cxlo = cell_of(qx - Rr), cxhi = cell_of(qx + Rr);
    const int cylo = cell_of(qy - Rr), cyhi = cell_of(qy + Rr);
    int base = 0;
    const unsigned lt_mask = (1u << lane) - 1u;
    for (int cy = cylo; cy <= cyhi; ++cy) {
        const int s = cstart[cy * CD + cxlo];
        const int e = cstart[cy * CD + cxhi + 1];
        for (int b = s; b < e; b += 32) {
            const int i = b + lane;
            const bool valid = (i < e);
            const float4 p = sref[valid ? i : s];
            const float r2 = sq3(p.x, p.y, p.z);
            const float cr = dot3_fma(qx, qy, qz, p.x, p.y, p.z);
            const float d  = __fmaf_rn(-2.0f, cr, __fadd_rn(q2, r2));
            const bool pred = valid && (d <= R2);
            const unsigned m = __ballot_sync(0xffffffffu, pred);
            if (pred) {
                const int pos = base + __popc(m & lt_mask);
                if (pos < BUF_CAP) wbuf[pos] = make_key(d, __float_as_int(p.w));
            }
            base += __popc(m);
        }
    }
    const int cnt = (base < BUF_CAP) ? base : BUF_CAP;   // >= 16 guaranteed
    __syncwarp();

    // 5. exact selection: 16 argmin-extract rounds (total-order keys)
    for (int sel = 0; sel < KNN_K; ++sel) {
        ull best = ~0ull;
        int bpos = -1;
        for (int i = lane; i < cnt; i += 32) {
            const ull v = wbuf[i];
            if (v < best) { best = v; bpos = i; }
        }
#pragma unroll
        for (int off = 16; off > 0; off >>= 1) {
            const ull ob = __shfl_down_sync(0xffffffffu, best, off);
            const int op = __shfl_down_sync(0xffffffffu, bpos, off);
            if (ob < best) { best = ob; bpos = op; }
        }
        bpos = __shfl_sync(0xffffffffu, bpos, 0);
        if (lane == 0) g_knn_idx[q * KNN_K + sel] = (int)(wbuf[bpos] & 0xffffffffu);
        if (lane == (bpos & 31)) wbuf[bpos] = ~0ull;
        __syncwarp();
    }
}

// One block per query. blockDim = (64, 4). Thread y owns neighbors 4y..4y+3:
// one int4 idx load -> 4 independent gathers (MLP=4), cur reused from regs.
__global__ void __launch_bounds__(256) gather_kernel(
        const float4* __restrict__ feat_prev,
        const float4* __restrict__ feat_cur,
        float4* __restrict__ out) {
    const int q  = blockIdx.x;
    const int c4 = threadIdx.x;   // 0..63
    const int y  = threadIdx.y;   // 0..3

    const float4 cur = feat_cur[q * C4 + c4];
    const int4 iv = __ldg((const int4*)(g_knn_idx + q * KNN_K + 4 * y));

    const float4 p0 = feat_prev[iv.x * C4 + c4];
    const float4 p1 = feat_prev[iv.y * C4 + c4];
    const float4 p2 = feat_prev[iv.z * C4 + c4];
    const float4 p3 = feat_prev[iv.w * C4 + c4];

    const int row0 = q * KNN_K + 4 * y;
#pragma unroll
    for (int jj = 0; jj < 4; ++jj) {
        const float4 p = (jj == 0) ? p0 : (jj == 1) ? p1 : (jj == 2) ? p2 : p3;
        float4 dv;
        dv.x = p.x - cur.x; dv.y = p.y - cur.y;
        dv.z = p.z - cur.z; dv.w = p.w - cur.w;
        const long long row = row0 + jj;
        __stcs(&out[row * 128 + c4], dv);
        __stcs(&out[row * 128 + C4 + c4], cur);
    }
}

extern "C" void kernel_launch(void* const* d_in, const int* in_sizes, int n_in,
                              void* d_out, int out_size) {
    const float*  xyz_prev  = (const float*)d_in[0];
    const float*  xyz_cur   = (const float*)d_in[1];
    const float4* feat_prev = (const float4*)d_in[2];
    const float4* feat_cur  = (const float4*)d_in[3];
    float4* out = (float4*)d_out;

    (void)in_sizes; (void)n_in; (void)out_size;

    const int smem = NR * sizeof(float4)             // refs        128 KB
                   + WPB * BUF_CAP * sizeof(ull)     // survivors    84 KB
                   + (C2 + 1 + C2) * sizeof(int);    // starts+cursors ~8 KB
    cudaFuncSetAttribute(knn_kernel, cudaFuncAttributeMaxDynamicSharedMemorySize, smem);

    knn_kernel<<<KNN_BLOCKS, THREADS, smem>>>(xyz_prev, xyz_cur);
    gather_kernel<<<NQ, dim3(64, 4)>>>(feat_prev, feat_cur, out);
}